// round 1
// baseline (speedup 1.0000x reference)
#include <cuda_runtime.h>
#include <cstdint>

static constexpr int B_ = 2, S_ = 2048, D_ = 1024, H_ = 16, HD_ = 64;
static constexpr int M_ROWS = B_ * S_;                 // 4096
static constexpr size_t BHSD = (size_t)B_ * H_ * S_ * HD_;

// Scratch (no cudaMalloc allowed): Q/K/V in [B,H,S,Hd], attn out in [B,S,D]
__device__ float g_Q[BHSD];
__device__ float g_K[BHSD];
__device__ float g_V[BHSD];
__device__ float g_att[(size_t)B_ * S_ * D_];

__device__ __forceinline__ uint32_t f2tf(float x) {
    uint32_t r;
    asm("cvt.rna.tf32.f32 %0, %1;" : "=r"(r) : "f"(x));
    return r;
}
__device__ __forceinline__ float f2tff(float x) { return __uint_as_float(f2tf(x)); }

__device__ __forceinline__ void mma8(float* c, const uint32_t* a, const uint32_t* b) {
    asm volatile(
        "mma.sync.aligned.m16n8k8.row.col.f32.tf32.tf32.f32 "
        "{%0,%1,%2,%3},{%4,%5,%6,%7},{%8,%9},{%0,%1,%2,%3};\n"
        : "+f"(c[0]), "+f"(c[1]), "+f"(c[2]), "+f"(c[3])
        : "r"(a[0]), "r"(a[1]), "r"(a[2]), "r"(a[3]), "r"(b[0]), "r"(b[1]));
}

// ============================================================================
// Generic TF32 GEMM: C = (A[M,K] @ B[K,N] + bias) * scale
// mode 0: C row-major [M,N]. mode 1: scatter to [B,H,S,Hd] (M=B*S, N=H*Hd).
// BM=128, BN=128, BK=32, 256 threads, warp grid 2(m) x 4(n), warp tile 64x32.
// ============================================================================
__global__ __launch_bounds__(256, 2)
void gemm_tf32(const float* __restrict__ A, const float* __restrict__ Bm,
               const float* __restrict__ bias, float* __restrict__ C,
               int M, int N, int Kd, float scale, int mode) {
    __shared__ float As[128][36];   // [m][k], pad->stride 36: conflict-free frag reads
    __shared__ float Bs[128][36];   // [n][k] (transposed on load)

    const int tid  = threadIdx.x;
    const int warp = tid >> 5, lane = tid & 31;
    const int g = lane >> 2, tg = lane & 3;
    const int wm = warp >> 2, wn = warp & 3;
    const int bm = blockIdx.y * 128, bn = blockIdx.x * 128;

    float acc[4][4][4] = {};

    for (int k0 = 0; k0 < Kd; k0 += 32) {
        // A tile: 128 x 32, float4 loads, tf32-round into smem
        #pragma unroll
        for (int i = tid; i < 1024; i += 256) {
            int r = i >> 3, c = (i & 7) << 2;
            float4 v = *(const float4*)(A + (size_t)(bm + r) * Kd + k0 + c);
            float* d = &As[r][c];
            d[0] = f2tff(v.x); d[1] = f2tff(v.y); d[2] = f2tff(v.z); d[3] = f2tff(v.w);
        }
        // B tile: 32 x 128 rows (k-major in gmem), store transposed [n][k]
        #pragma unroll
        for (int i = tid; i < 1024; i += 256) {
            int r = i >> 5, c = (i & 31) << 2;
            float4 v = *(const float4*)(Bm + (size_t)(k0 + r) * N + bn + c);
            Bs[c + 0][r] = f2tff(v.x);
            Bs[c + 1][r] = f2tff(v.y);
            Bs[c + 2][r] = f2tff(v.z);
            Bs[c + 3][r] = f2tff(v.w);
        }
        __syncthreads();

        #pragma unroll
        for (int kk = 0; kk < 32; kk += 8) {
            uint32_t af[4][4], bf[4][2];
            #pragma unroll
            for (int mt = 0; mt < 4; ++mt) {
                int r0 = wm * 64 + mt * 16;
                af[mt][0] = __float_as_uint(As[r0 + g][kk + tg]);
                af[mt][1] = __float_as_uint(As[r0 + g + 8][kk + tg]);
                af[mt][2] = __float_as_uint(As[r0 + g][kk + tg + 4]);
                af[mt][3] = __float_as_uint(As[r0 + g + 8][kk + tg + 4]);
            }
            #pragma unroll
            for (int nt = 0; nt < 4; ++nt) {
                int c0 = wn * 32 + nt * 8;
                bf[nt][0] = __float_as_uint(Bs[c0 + g][kk + tg]);
                bf[nt][1] = __float_as_uint(Bs[c0 + g][kk + tg + 4]);
            }
            #pragma unroll
            for (int mt = 0; mt < 4; ++mt)
                #pragma unroll
                for (int nt = 0; nt < 4; ++nt)
                    mma8(acc[mt][nt], af[mt], bf[nt]);
        }
        __syncthreads();
    }

    // Epilogue
    #pragma unroll
    for (int mt = 0; mt < 4; ++mt) {
        #pragma unroll
        for (int nt = 0; nt < 4; ++nt) {
            int r0 = bm + wm * 64 + mt * 16 + g;
            int c0 = bn + wn * 32 + nt * 8 + tg * 2;
            #pragma unroll
            for (int e = 0; e < 4; ++e) {
                int r = r0 + (e >> 1) * 8;
                int c = c0 + (e & 1);
                float v = (acc[mt][nt][e] + bias[c]) * scale;
                if (mode == 0) {
                    C[(size_t)r * N + c] = v;
                } else {
                    int b = r >> 11, s = r & (S_ - 1);
                    int h = c >> 6, d = c & (HD_ - 1);
                    C[(((size_t)(b * H_ + h) * S_) + s) * HD_ + d] = v;
                }
            }
        }
    }
}

// ============================================================================
// Flash attention: one CTA per (b*h, q-tile of 128). Hd = 64, 16 key tiles of 128.
// Smem: Qs/Ks/Vs [128][68] tf32-as-float, Ss [128][129] scores/P, row stats.
// QK warp grid 2(m)x4(n); PV warp grid 4(m)x2(n); O accum in registers (fp32).
// Softmax scale is pre-baked into Q by the projection GEMM.
// ============================================================================
static constexpr int QKV_STRIDE = 68;    // 64 + 4 pad: conflict-free frag reads
static constexpr int SS_STRIDE  = 129;   // odd: conflict-free row-wise softmax
static constexpr int ATT_SMEM_FLOATS = 3 * 128 * QKV_STRIDE + 128 * SS_STRIDE + 3 * 128;
static constexpr int ATT_SMEM_BYTES  = ATT_SMEM_FLOATS * 4;  // 172,032 B

__global__ __launch_bounds__(256, 1)
void attn_kernel(const float* __restrict__ Q, const float* __restrict__ K,
                 const float* __restrict__ V, float* __restrict__ O) {
    extern __shared__ float sm[];
    float* Qs   = sm;
    float* Ks   = Qs + 128 * QKV_STRIDE;
    float* Vs   = Ks + 128 * QKV_STRIDE;
    float* Ss   = Vs + 128 * QKV_STRIDE;
    float* rowm = Ss + 128 * SS_STRIDE;
    float* rowl = rowm + 128;
    float* ralp = rowl + 128;

    const int tid  = threadIdx.x;
    const int warp = tid >> 5, lane = tid & 31;
    const int g = lane >> 2, tg = lane & 3;
    const int bh = blockIdx.y, qt = blockIdx.x;

    const float* Qp = Q + ((size_t)bh * S_ + qt * 128) * HD_;
    const float* Kp = K + (size_t)bh * S_ * HD_;
    const float* Vp = V + (size_t)bh * S_ * HD_;

    // Load Q tile (128 x 64), tf32-rounded
    #pragma unroll
    for (int i = tid; i < 128 * 16; i += 256) {
        int r = i >> 4, c = (i & 15) << 2;
        float4 v = *(const float4*)(Qp + r * HD_ + c);
        float* d = Qs + r * QKV_STRIDE + c;
        d[0] = f2tff(v.x); d[1] = f2tff(v.y); d[2] = f2tff(v.z); d[3] = f2tff(v.w);
    }
    if (tid < 128) { rowm[tid] = -1e30f; rowl[tid] = 0.f; }

    float oacc[2][4][4] = {};

    const int wmq = warp >> 2, wnq = warp & 3;   // QK: m-warp 64, n-warp 32
    const int wmp = warp >> 1, wnp = warp & 1;   // PV: m-warp 32, n-warp 32

    for (int kt = 0; kt < S_ / 128; ++kt) {
        const float* Kt = Kp + (size_t)kt * 128 * HD_;
        const float* Vt = Vp + (size_t)kt * 128 * HD_;
        #pragma unroll
        for (int i = tid; i < 128 * 16; i += 256) {
            int r = i >> 4, c = (i & 15) << 2;
            float4 kv = *(const float4*)(Kt + r * HD_ + c);
            float4 vv = *(const float4*)(Vt + r * HD_ + c);
            float* dk = Ks + r * QKV_STRIDE + c;
            dk[0] = f2tff(kv.x); dk[1] = f2tff(kv.y); dk[2] = f2tff(kv.z); dk[3] = f2tff(kv.w);
            float* dv = Vs + r * QKV_STRIDE + c;
            dv[0] = f2tff(vv.x); dv[1] = f2tff(vv.y); dv[2] = f2tff(vv.z); dv[3] = f2tff(vv.w);
        }
        __syncthreads();

        // S = Q @ K^T (scale already in Q)
        float sacc[4][4][4] = {};
        #pragma unroll
        for (int kk = 0; kk < HD_; kk += 8) {
            uint32_t af[4][4], bf[4][2];
            #pragma unroll
            for (int mt = 0; mt < 4; ++mt) {
                const float* a = Qs + (wmq * 64 + mt * 16) * QKV_STRIDE + kk;
                af[mt][0] = __float_as_uint(a[g * QKV_STRIDE + tg]);
                af[mt][1] = __float_as_uint(a[(g + 8) * QKV_STRIDE + tg]);
                af[mt][2] = __float_as_uint(a[g * QKV_STRIDE + tg + 4]);
                af[mt][3] = __float_as_uint(a[(g + 8) * QKV_STRIDE + tg + 4]);
            }
            #pragma unroll
            for (int nt = 0; nt < 4; ++nt) {
                const float* b = Ks + (wnq * 32 + nt * 8) * QKV_STRIDE + kk;
                bf[nt][0] = __float_as_uint(b[g * QKV_STRIDE + tg]);
                bf[nt][1] = __float_as_uint(b[g * QKV_STRIDE + tg + 4]);
            }
            #pragma unroll
            for (int mt = 0; mt < 4; ++mt)
                #pragma unroll
                for (int nt = 0; nt < 4; ++nt)
                    mma8(sacc[mt][nt], af[mt], bf[nt]);
        }
        // Spill S tile to smem
        #pragma unroll
        for (int mt = 0; mt < 4; ++mt) {
            int r0 = wmq * 64 + mt * 16 + g;
            #pragma unroll
            for (int nt = 0; nt < 4; ++nt) {
                int c0 = wnq * 32 + nt * 8 + tg * 2;
                Ss[r0 * SS_STRIDE + c0]           = sacc[mt][nt][0];
                Ss[r0 * SS_STRIDE + c0 + 1]       = sacc[mt][nt][1];
                Ss[(r0 + 8) * SS_STRIDE + c0]     = sacc[mt][nt][2];
                Ss[(r0 + 8) * SS_STRIDE + c0 + 1] = sacc[mt][nt][3];
            }
        }
        __syncthreads();

        // Online softmax (one thread per row; SS_STRIDE=129 -> conflict-free)
        if (tid < 128) {
            float mo = rowm[tid];
            float mx = mo;
            float* sr = Ss + tid * SS_STRIDE;
            #pragma unroll 8
            for (int j = 0; j < 128; ++j) mx = fmaxf(mx, sr[j]);
            float al = __expf(mo - mx);
            float sum = 0.f;
            #pragma unroll 8
            for (int j = 0; j < 128; ++j) {
                float p = __expf(sr[j] - mx);
                sum += p;
                sr[j] = f2tff(p);   // P stored tf32-rounded for the PV mma
            }
            rowm[tid] = mx;
            rowl[tid] = rowl[tid] * al + sum;
            ralp[tid] = al;
        }
        __syncthreads();

        // Rescale O accumulators, then O += P @ V
        #pragma unroll
        for (int mt = 0; mt < 2; ++mt) {
            int r0 = wmp * 32 + mt * 16 + g;
            float a0 = ralp[r0], a1 = ralp[r0 + 8];
            #pragma unroll
            for (int nt = 0; nt < 4; ++nt) {
                oacc[mt][nt][0] *= a0; oacc[mt][nt][1] *= a0;
                oacc[mt][nt][2] *= a1; oacc[mt][nt][3] *= a1;
            }
        }
        #pragma unroll
        for (int kk = 0; kk < 128; kk += 8) {
            uint32_t af[2][4], bf[4][2];
            #pragma unroll
            for (int mt = 0; mt < 2; ++mt) {
                const float* a = Ss + (wmp * 32 + mt * 16) * SS_STRIDE + kk;
                af[mt][0] = __float_as_uint(a[g * SS_STRIDE + tg]);
                af[mt][1] = __float_as_uint(a[(g + 8) * SS_STRIDE + tg]);
                af[mt][2] = __float_as_uint(a[g * SS_STRIDE + tg + 4]);
                af[mt][3] = __float_as_uint(a[(g + 8) * SS_STRIDE + tg + 4]);
            }
            #pragma unroll
            for (int nt = 0; nt < 4; ++nt) {
                const float* b = Vs + kk * QKV_STRIDE + wnp * 32 + nt * 8 + g;
                bf[nt][0] = __float_as_uint(b[tg * QKV_STRIDE]);
                bf[nt][1] = __float_as_uint(b[(tg + 4) * QKV_STRIDE]);
            }
            #pragma unroll
            for (int mt = 0; mt < 2; ++mt)
                #pragma unroll
                for (int nt = 0; nt < 4; ++nt)
                    mma8(oacc[mt][nt], af[mt], bf[nt]);
        }
        __syncthreads();
    }

    if (tid < 128) ralp[tid] = 1.f / rowl[tid];
    __syncthreads();

    // Write O to [B,S,D] (head h occupies cols h*64..h*64+63)
    const int b = bh >> 4, h = bh & (H_ - 1);
    float* Op = O + ((size_t)b * S_ + qt * 128) * D_ + h * HD_;
    #pragma unroll
    for (int mt = 0; mt < 2; ++mt) {
        #pragma unroll
        for (int nt = 0; nt < 4; ++nt) {
            int r0 = wmp * 32 + mt * 16 + g;
            int c0 = wnp * 32 + nt * 8 + tg * 2;
            float i0 = ralp[r0], i1 = ralp[r0 + 8];
            Op[(size_t)r0 * D_ + c0]           = oacc[mt][nt][0] * i0;
            Op[(size_t)r0 * D_ + c0 + 1]       = oacc[mt][nt][1] * i0;
            Op[(size_t)(r0 + 8) * D_ + c0]     = oacc[mt][nt][2] * i1;
            Op[(size_t)(r0 + 8) * D_ + c0 + 1] = oacc[mt][nt][3] * i1;
        }
    }
}

// ============================================================================
extern "C" void kernel_launch(void* const* d_in, const int* in_sizes, int n_in,
                              void* d_out, int out_size) {
    (void)in_sizes; (void)n_in; (void)out_size;
    const float* x  = (const float*)d_in[0];
    const float* Wq = (const float*)d_in[1];
    const float* bq = (const float*)d_in[2];
    const float* Wk = (const float*)d_in[3];
    const float* bk = (const float*)d_in[4];
    const float* Wv = (const float*)d_in[5];
    const float* bv = (const float*)d_in[6];
    const float* Wo = (const float*)d_in[7];
    const float* bo = (const float*)d_in[8];
    float* out = (float*)d_out;

    float *Qb, *Kb, *Vb, *Ab;
    cudaGetSymbolAddress((void**)&Qb, g_Q);
    cudaGetSymbolAddress((void**)&Kb, g_K);
    cudaGetSymbolAddress((void**)&Vb, g_V);
    cudaGetSymbolAddress((void**)&Ab, g_att);

    const dim3 gproj(D_ / 128, M_ROWS / 128);  // (8, 32)
    const float qscale = 0.125f;               // Hd^-0.5, baked into Q

    gemm_tf32<<<gproj, 256>>>(x, Wq, bq, Qb, M_ROWS, D_, D_, qscale, 1);
    gemm_tf32<<<gproj, 256>>>(x, Wk, bk, Kb, M_ROWS, D_, D_, 1.0f, 1);
    gemm_tf32<<<gproj, 256>>>(x, Wv, bv, Vb, M_ROWS, D_, D_, 1.0f, 1);

    cudaFuncSetAttribute(attn_kernel, cudaFuncAttributeMaxDynamicSharedMemorySize,
                         ATT_SMEM_BYTES);
    attn_kernel<<<dim3(S_ / 128, B_ * H_), 256, ATT_SMEM_BYTES>>>(Qb, Kb, Vb, Ab);

    gemm_tf32<<<gproj, 256>>>(Ab, Wo, bo, out, M_ROWS, D_, D_, 1.0f, 0);
}

// round 5
// speedup vs baseline: 1.8784x; 1.8784x over previous
#include <cuda_runtime.h>
#include <cstdint>

static constexpr int B_ = 2, S_ = 2048, D_ = 1024, H_ = 16, HD_ = 64;
static constexpr int M_ROWS = B_ * S_;                 // 4096
static constexpr size_t BHSD = (size_t)B_ * H_ * S_ * HD_;

// Scratch (no cudaMalloc allowed)
__device__ float g_Q[BHSD];
__device__ float g_K[BHSD];
__device__ float g_V[BHSD];
__device__ float g_att[(size_t)B_ * S_ * D_];
__device__ float g_x [(size_t)M_ROWS * D_];
__device__ float g_Wq[(size_t)D_ * D_];
__device__ float g_Wk[(size_t)D_ * D_];
__device__ float g_Wv[(size_t)D_ * D_];
__device__ float g_Wo[(size_t)D_ * D_];

__device__ __forceinline__ uint32_t f2tf(float x) {
    uint32_t r;
    asm("cvt.rna.tf32.f32 %0, %1;" : "=r"(r) : "f"(x));
    return r;
}
__device__ __forceinline__ float f2tff(float x) { return __uint_as_float(f2tf(x)); }

__device__ __forceinline__ void mma8(float* c, const uint32_t* a, const uint32_t* b) {
    asm volatile(
        "mma.sync.aligned.m16n8k8.row.col.f32.tf32.tf32.f32 "
        "{%0,%1,%2,%3},{%4,%5,%6,%7},{%8,%9},{%0,%1,%2,%3};\n"
        : "+f"(c[0]), "+f"(c[1]), "+f"(c[2]), "+f"(c[3])
        : "r"(a[0]), "r"(a[1]), "r"(a[2]), "r"(a[3]), "r"(b[0]), "r"(b[1]));
}
__device__ __forceinline__ void mma8f(float* c, const float* a, float b0, float b1) {
    uint32_t af[4] = {__float_as_uint(a[0]), __float_as_uint(a[1]),
                      __float_as_uint(a[2]), __float_as_uint(a[3])};
    uint32_t bf[2] = {__float_as_uint(b0), __float_as_uint(b1)};
    mma8(c, af, bf);
}

__device__ __forceinline__ void cp16(uint32_t d, const void* s) {
    asm volatile("cp.async.cg.shared.global [%0], [%1], 16;\n" :: "r"(d), "l"(s));
}
__device__ __forceinline__ void cp_commit() { asm volatile("cp.async.commit_group;\n"); }
template <int N> __device__ __forceinline__ void cp_wait() {
    asm volatile("cp.async.wait_group %0;\n" :: "n"(N));
}

// ============================================================================
// Elementwise tf32 pre-rounding
// ============================================================================
__global__ void round_tf32_kernel(const float* __restrict__ src,
                                  float* __restrict__ dst, int n) {
    int i = (blockIdx.x * blockDim.x + threadIdx.x) * 4;
    if (i < n) {
        float4 v = *(const float4*)(src + i);
        v.x = f2tff(v.x); v.y = f2tff(v.y); v.z = f2tff(v.z); v.w = f2tff(v.w);
        *(float4*)(dst + i) = v;
    }
}

// ============================================================================
// TF32 GEMM, fixed shape 4096x1024x1024, cp.async 2-stage pipeline.
// A smem [m][k] stride 36, B smem [k][n] stride 136. Inputs pre-rounded tf32.
// mode 0: plain store. mode 1: scatter to [B,H,S,Hd], store tf32-rounded.
// ============================================================================
static constexpr int GEMM_SMEM = (2 * 128 * 36 + 2 * 32 * 136) * 4;  // 71680 B

__global__ __launch_bounds__(256, 2)
void gemm_tf32(const float* __restrict__ A, const float* __restrict__ Bm,
               const float* __restrict__ bias, float* __restrict__ C,
               float scale, int mode) {
    constexpr int Kd = 1024, N = 1024, NT = Kd / 32;
    extern __shared__ float sh[];
    float* As = sh;                    // [2][128*36]
    float* Bs = sh + 2 * 128 * 36;     // [2][32*136]
    const uint32_t sA = (uint32_t)__cvta_generic_to_shared(As);
    const uint32_t sB = (uint32_t)__cvta_generic_to_shared(Bs);

    const int tid  = threadIdx.x;
    const int warp = tid >> 5, lane = tid & 31;
    const int g = lane >> 2, tg = lane & 3;
    const int wm = warp >> 2, wn = warp & 3;
    const int bm = blockIdx.y * 128, bn = blockIdx.x * 128;

    auto issue = [&](int kt, int st) {
        #pragma unroll
        for (int j = 0; j < 4; ++j) {                   // A: 128x32 = 1024 chunks
            int cc = tid + j * 256;
            int r = cc >> 3, o = cc & 7;
            cp16(sA + (uint32_t)(st * 128 * 36 + r * 36 + o * 4) * 4,
                 A + (size_t)(bm + r) * Kd + kt * 32 + o * 4);
        }
        #pragma unroll
        for (int j = 0; j < 4; ++j) {                   // B: 32x128 = 1024 chunks
            int cc = tid + j * 256;
            int k = cc >> 5, o = cc & 31;
            cp16(sB + (uint32_t)(st * 32 * 136 + k * 136 + o * 4) * 4,
                 Bm + (size_t)(kt * 32 + k) * N + bn + o * 4);
        }
        cp_commit();
    };

    float acc[4][4][4] = {};
    issue(0, 0);

    for (int kt = 0; kt < NT; ++kt) {
        if (kt + 1 < NT) { issue(kt + 1, (kt + 1) & 1); cp_wait<1>(); }
        else             { cp_wait<0>(); }
        __syncthreads();
        const float* as = As + (kt & 1) * 128 * 36;
        const float* bs = Bs + (kt & 1) * 32 * 136;

        #pragma unroll
        for (int kk = 0; kk < 32; kk += 8) {
            uint32_t af[4][4], bf[4][2];
            #pragma unroll
            for (int mt = 0; mt < 4; ++mt) {
                const float* a = as + (wm * 64 + mt * 16) * 36 + kk;
                af[mt][0] = __float_as_uint(a[g * 36 + tg]);
                af[mt][1] = __float_as_uint(a[(g + 8) * 36 + tg]);
                af[mt][2] = __float_as_uint(a[g * 36 + tg + 4]);
                af[mt][3] = __float_as_uint(a[(g + 8) * 36 + tg + 4]);
            }
            #pragma unroll
            for (int nt = 0; nt < 4; ++nt) {
                const float* b = bs + kk * 136 + wn * 32 + nt * 8 + g;
                bf[nt][0] = __float_as_uint(b[tg * 136]);
                bf[nt][1] = __float_as_uint(b[(tg + 4) * 136]);
            }
            #pragma unroll
            for (int mt = 0; mt < 4; ++mt)
                #pragma unroll
                for (int nt = 0; nt < 4; ++nt)
                    mma8(acc[mt][nt], af[mt], bf[nt]);
        }
        __syncthreads();
    }

    #pragma unroll
    for (int mt = 0; mt < 4; ++mt) {
        #pragma unroll
        for (int nt = 0; nt < 4; ++nt) {
            int r0 = bm + wm * 64 + mt * 16 + g;
            int c0 = bn + wn * 32 + nt * 8 + tg * 2;
            #pragma unroll
            for (int e = 0; e < 4; ++e) {
                int r = r0 + (e >> 1) * 8;
                int c = c0 + (e & 1);
                float v = (acc[mt][nt][e] + bias[c]) * scale;
                if (mode == 0) {
                    C[(size_t)r * N + c] = v;
                } else {
                    int b = r >> 11, s = r & (S_ - 1);
                    int h = c >> 6, d = c & (HD_ - 1);
                    C[(((size_t)(b * H_ + h) * S_) + s) * HD_ + d] = f2tff(v);
                }
            }
        }
    }
}

// ============================================================================
// Flash attention, register softmax, P via per-warp smem round-trip.
// CTA = 128 q-rows, 8 warps each own 16 rows x full 128 S-cols.
// K/V double-buffered via cp.async. Inputs pre-rounded tf32.
// Smem: K [2][128][68], V [2][128][72], P per-warp [16][132].
// ============================================================================
static constexpr int KSS = 68, VSS = 72, PSS = 132;
static constexpr int ATT_SMEM =
    (2 * 128 * KSS + 2 * 128 * VSS + 8 * 16 * PSS) * 4;  // 210944 B

__global__ __launch_bounds__(256, 1)
void attn_kernel(const float* __restrict__ Q, const float* __restrict__ K,
                 const float* __restrict__ V, float* __restrict__ O) {
    extern __shared__ float sh[];
    float* Ksf = sh;                       // [2][128*KSS]
    float* Vsf = sh + 2 * 128 * KSS;       // [2][128*VSS]
    float* Ps  = Vsf + 2 * 128 * VSS;      // [8][16*PSS]
    const uint32_t sK = (uint32_t)__cvta_generic_to_shared(Ksf);
    const uint32_t sV = (uint32_t)__cvta_generic_to_shared(Vsf);

    const int tid  = threadIdx.x;
    const int warp = tid >> 5, lane = tid & 31;
    const int g = lane >> 2, tg = lane & 3;
    const int bh = blockIdx.y, qt = blockIdx.x;

    const float* Qp = Q + ((size_t)bh * S_ + qt * 128) * HD_;
    const float* Kp = K + (size_t)bh * S_ * HD_;
    const float* Vp = V + (size_t)bh * S_ * HD_;

    auto issue = [&](int kt, int st) {
        const float* Kt = Kp + (size_t)kt * 128 * HD_;
        const float* Vt = Vp + (size_t)kt * 128 * HD_;
        #pragma unroll
        for (int j = 0; j < 8; ++j) {       // FIX: 2048 chunks = full 128x64 tile
            int cc = tid + j * 256;
            int r = cc >> 4, o = cc & 15;
            cp16(sK + (uint32_t)(st * 128 * KSS + r * KSS + o * 4) * 4, Kt + r * 64 + o * 4);
            cp16(sV + (uint32_t)(st * 128 * VSS + r * VSS + o * 4) * 4, Vt + r * 64 + o * 4);
        }
        cp_commit();
    };

    issue(0, 0);

    // Stage Q through K stage-1 buffer (not yet loaded), build Q A-frags.
    float* Qst = Ksf + 128 * KSS;
    #pragma unroll
    for (int i = tid; i < 2048; i += 256) {
        int r = i >> 4, c4 = i & 15;
        float4 v = *(const float4*)(Qp + r * 64 + c4 * 4);
        *(float4*)(Qst + r * KSS + c4 * 4) = v;
    }
    __syncthreads();
    float qf[8][4];
    #pragma unroll
    for (int kk = 0; kk < 8; ++kk) {
        const float* q = Qst + (warp * 16) * KSS + kk * 8;
        qf[kk][0] = q[g * KSS + tg];
        qf[kk][1] = q[(g + 8) * KSS + tg];
        qf[kk][2] = q[g * KSS + tg + 4];
        qf[kk][3] = q[(g + 8) * KSS + tg + 4];
    }
    __syncthreads();

    float m0 = -1e30f, m1 = -1e30f, l0 = 0.f, l1 = 0.f;
    float oacc[8][4] = {};
    float* Pw = Ps + warp * 16 * PSS;      // warp-private P tile [16][PSS]

    constexpr int NT = S_ / 128;
    for (int kt = 0; kt < NT; ++kt) {
        if (kt + 1 < NT) { issue(kt + 1, (kt + 1) & 1); cp_wait<1>(); }
        else             { cp_wait<0>(); }
        __syncthreads();
        const float* Ksb = Ksf + (kt & 1) * 128 * KSS;
        const float* Vsb = Vsf + (kt & 1) * 128 * VSS;

        // S = Q @ K^T : 16 rows x 128 cols per warp
        float sacc[16][4] = {};
        #pragma unroll
        for (int nt = 0; nt < 16; ++nt) {
            const float* kb = Ksb + (nt * 8 + g) * KSS;
            #pragma unroll
            for (int kk = 0; kk < 8; ++kk)
                mma8f(sacc[nt], qf[kk], kb[kk * 8 + tg], kb[kk * 8 + tg + 4]);
        }

        // Register softmax over the warp's 16 rows (rows g / g+8 per lane)
        float mx0 = -1e30f, mx1 = -1e30f;
        #pragma unroll
        for (int nt = 0; nt < 16; ++nt) {
            mx0 = fmaxf(mx0, fmaxf(sacc[nt][0], sacc[nt][1]));
            mx1 = fmaxf(mx1, fmaxf(sacc[nt][2], sacc[nt][3]));
        }
        mx0 = fmaxf(mx0, __shfl_xor_sync(0xffffffffu, mx0, 1));
        mx0 = fmaxf(mx0, __shfl_xor_sync(0xffffffffu, mx0, 2));
        mx1 = fmaxf(mx1, __shfl_xor_sync(0xffffffffu, mx1, 1));
        mx1 = fmaxf(mx1, __shfl_xor_sync(0xffffffffu, mx1, 2));
        float nm0 = fmaxf(m0, mx0), nm1 = fmaxf(m1, mx1);
        float al0 = __expf(m0 - nm0), al1 = __expf(m1 - nm1);
        m0 = nm0; m1 = nm1;

        float s0 = 0.f, s1 = 0.f;
        #pragma unroll
        for (int nt = 0; nt < 16; ++nt) {
            float p0 = __expf(sacc[nt][0] - m0);
            float p1 = __expf(sacc[nt][1] - m0);
            float p2 = __expf(sacc[nt][2] - m1);
            float p3 = __expf(sacc[nt][3] - m1);
            s0 += p0 + p1; s1 += p2 + p3;
            // C-frag spill to warp-private smem
            Pw[g * PSS + nt * 8 + 2 * tg]           = f2tff(p0);
            Pw[g * PSS + nt * 8 + 2 * tg + 1]       = f2tff(p1);
            Pw[(g + 8) * PSS + nt * 8 + 2 * tg]     = f2tff(p2);
            Pw[(g + 8) * PSS + nt * 8 + 2 * tg + 1] = f2tff(p3);
        }
        s0 += __shfl_xor_sync(0xffffffffu, s0, 1);
        s0 += __shfl_xor_sync(0xffffffffu, s0, 2);
        s1 += __shfl_xor_sync(0xffffffffu, s1, 1);
        s1 += __shfl_xor_sync(0xffffffffu, s1, 2);
        l0 = l0 * al0 + s0;
        l1 = l1 * al1 + s1;
        __syncwarp();

        // Read P back as A-frags (warp-local)
        #pragma unroll
        for (int kk = 0; kk < 16; ++kk) {
            const float* p = Pw + kk * 8;
            sacc[kk][0] = p[g * PSS + tg];
            sacc[kk][1] = p[(g + 8) * PSS + tg];
            sacc[kk][2] = p[g * PSS + tg + 4];
            sacc[kk][3] = p[(g + 8) * PSS + tg + 4];
        }

        // O rescale + O += P @ V
        #pragma unroll
        for (int nt = 0; nt < 8; ++nt) {
            oacc[nt][0] *= al0; oacc[nt][1] *= al0;
            oacc[nt][2] *= al1; oacc[nt][3] *= al1;
        }
        #pragma unroll
        for (int nt = 0; nt < 8; ++nt) {
            #pragma unroll
            for (int kk = 0; kk < 16; ++kk) {
                const float* vb = Vsb + kk * 8 * VSS + nt * 8 + g;
                mma8f(oacc[nt], sacc[kk], vb[tg * VSS], vb[(tg + 4) * VSS]);
            }
        }
        __syncthreads();
    }

    const float inv0 = 1.f / l0, inv1 = 1.f / l1;
    const int b = bh >> 4, h = bh & (H_ - 1);
    const int r0 = qt * 128 + warp * 16 + g;
    float* Op = O + ((size_t)b * S_ + r0) * D_ + h * HD_;
    #pragma unroll
    for (int nt = 0; nt < 8; ++nt) {
        float2 t0 = make_float2(f2tff(oacc[nt][0] * inv0), f2tff(oacc[nt][1] * inv0));
        float2 t1 = make_float2(f2tff(oacc[nt][2] * inv1), f2tff(oacc[nt][3] * inv1));
        *(float2*)(Op + nt * 8 + 2 * tg) = t0;
        *(float2*)(Op + (size_t)8 * D_ + nt * 8 + 2 * tg) = t1;
    }
}

// ============================================================================
extern "C" void kernel_launch(void* const* d_in, const int* in_sizes, int n_in,
                              void* d_out, int out_size) {
    (void)in_sizes; (void)n_in; (void)out_size;
    const float* x  = (const float*)d_in[0];
    const float* Wq = (const float*)d_in[1];
    const float* bq = (const float*)d_in[2];
    const float* Wk = (const float*)d_in[3];
    const float* bk = (const float*)d_in[4];
    const float* Wv = (const float*)d_in[5];
    const float* bv = (const float*)d_in[6];
    const float* Wo = (const float*)d_in[7];
    const float* bo = (const float*)d_in[8];
    float* out = (float*)d_out;

    float *Qb, *Kb, *Vb, *Ab, *Xr, *Wqr, *Wkr, *Wvr, *Wor;
    cudaGetSymbolAddress((void**)&Qb, g_Q);
    cudaGetSymbolAddress((void**)&Kb, g_K);
    cudaGetSymbolAddress((void**)&Vb, g_V);
    cudaGetSymbolAddress((void**)&Ab, g_att);
    cudaGetSymbolAddress((void**)&Xr, g_x);
    cudaGetSymbolAddress((void**)&Wqr, g_Wq);
    cudaGetSymbolAddress((void**)&Wkr, g_Wk);
    cudaGetSymbolAddress((void**)&Wvr, g_Wv);
    cudaGetSymbolAddress((void**)&Wor, g_Wo);

    // tf32 pre-rounding
    const int nX = M_ROWS * D_, nW = D_ * D_;
    round_tf32_kernel<<<nX / 1024, 256>>>(x,  Xr,  nX);
    round_tf32_kernel<<<nW / 1024, 256>>>(Wq, Wqr, nW);
    round_tf32_kernel<<<nW / 1024, 256>>>(Wk, Wkr, nW);
    round_tf32_kernel<<<nW / 1024, 256>>>(Wv, Wvr, nW);
    round_tf32_kernel<<<nW / 1024, 256>>>(Wo, Wor, nW);

    cudaFuncSetAttribute(gemm_tf32, cudaFuncAttributeMaxDynamicSharedMemorySize, GEMM_SMEM);
    cudaFuncSetAttribute(attn_kernel, cudaFuncAttributeMaxDynamicSharedMemorySize, ATT_SMEM);

    const dim3 gproj(D_ / 128, M_ROWS / 128);  // (8, 32)
    const float qscale = 0.125f;               // Hd^-0.5, baked into Q

    gemm_tf32<<<gproj, 256, GEMM_SMEM>>>(Xr, Wqr, bq, Qb, qscale, 1);
    gemm_tf32<<<gproj, 256, GEMM_SMEM>>>(Xr, Wkr, bk, Kb, 1.0f, 1);
    gemm_tf32<<<gproj, 256, GEMM_SMEM>>>(Xr, Wvr, bv, Vb, 1.0f, 1);

    attn_kernel<<<dim3(S_ / 128, B_ * H_), 256, ATT_SMEM>>>(Qb, Kb, Vb, Ab);

    gemm_tf32<<<gproj, 256, GEMM_SMEM>>>(Ab, Wor, bo, out, 1.0f, 0);
}

// round 7
// speedup vs baseline: 2.0256x; 1.0783x over previous
#include <cuda_runtime.h>
#include <cstdint>

static constexpr int B_ = 2, S_ = 2048, D_ = 1024, H_ = 16, HD_ = 64;
static constexpr int M_ROWS = B_ * S_;                 // 4096
static constexpr size_t BHSD = (size_t)B_ * H_ * S_ * HD_;

// Scratch (no cudaMalloc allowed)
__device__ float g_Q[BHSD];
__device__ float g_K[BHSD];
__device__ float g_V[BHSD];
__device__ float g_att[(size_t)B_ * S_ * D_];   // k-permuted layout
__device__ float g_x [(size_t)M_ROWS * D_];     // k-permuted layout
__device__ float g_Wq[(size_t)D_ * D_];         // W^T, k-permuted, tf32
__device__ float g_Wk[(size_t)D_ * D_];
__device__ float g_Wv[(size_t)D_ * D_];
__device__ float g_Wo[(size_t)D_ * D_];

// k-permutation within each 8-block: value k stored at position PERM[k&7].
// Inverse: position p holds k = {0,4,1,5,2,6,3,7}[p&7]  =>  positions (2t,2t+1)
// hold k-values (t, t+4), making mma frag pairs contiguous (float2 loads).
__device__ static constexpr int KPERM[8] = {0, 2, 4, 6, 1, 3, 5, 7};

__device__ __forceinline__ uint32_t f2tf(float x) {
    uint32_t r;
    asm("cvt.rna.tf32.f32 %0, %1;" : "=r"(r) : "f"(x));
    return r;
}
__device__ __forceinline__ float f2tff(float x) { return __uint_as_float(f2tf(x)); }

__device__ __forceinline__ void mma8(float* c, const uint32_t* a, const uint32_t* b) {
    asm volatile(
        "mma.sync.aligned.m16n8k8.row.col.f32.tf32.tf32.f32 "
        "{%0,%1,%2,%3},{%4,%5,%6,%7},{%8,%9},{%0,%1,%2,%3};\n"
        : "+f"(c[0]), "+f"(c[1]), "+f"(c[2]), "+f"(c[3])
        : "r"(a[0]), "r"(a[1]), "r"(a[2]), "r"(a[3]), "r"(b[0]), "r"(b[1]));
}
__device__ __forceinline__ void mma8f(float* c, const float* a, float b0, float b1) {
    uint32_t af[4] = {__float_as_uint(a[0]), __float_as_uint(a[1]),
                      __float_as_uint(a[2]), __float_as_uint(a[3])};
    uint32_t bf[2] = {__float_as_uint(b0), __float_as_uint(b1)};
    mma8(c, af, bf);
}

__device__ __forceinline__ void cp16(uint32_t d, const void* s) {
    asm volatile("cp.async.cg.shared.global [%0], [%1], 16;\n" :: "r"(d), "l"(s));
}
__device__ __forceinline__ void cp_commit() { asm volatile("cp.async.commit_group;\n"); }
template <int N> __device__ __forceinline__ void cp_wait() {
    asm volatile("cp.async.wait_group %0;\n" :: "n"(N));
}

// ============================================================================
// x pre-rounding + k-permute: dst[(i&~7)|KPERM[i&7]] = tf32(src[i])
// i is a multiple of 4, so the 4 elements go to stride-2 positions.
// ============================================================================
__global__ void round_perm_kernel(const float* __restrict__ src,
                                  float* __restrict__ dst, int n) {
    int i = (blockIdx.x * blockDim.x + threadIdx.x) * 4;
    if (i < n) {
        float4 v = *(const float4*)(src + i);
        float* d = dst + ((i & ~7) | ((i & 4) ? 1 : 0));
        d[0] = f2tff(v.x); d[2] = f2tff(v.y); d[4] = f2tff(v.z); d[6] = f2tff(v.w);
    }
}

// ============================================================================
// Weight transpose + tf32 round + k-permute: Wt[n][pi(k)] = tf32(W[k][n])
// ============================================================================
__global__ void transpose_round_kernel(const float* __restrict__ W,
                                       float* __restrict__ Wt) {
    __shared__ float t[32][33];
    const int tx = threadIdx.x & 31, ty = threadIdx.x >> 5;   // 32x8
    const int bx = blockIdx.x * 32, by = blockIdx.y * 32;
    #pragma unroll
    for (int dy = 0; dy < 32; dy += 8)
        t[ty + dy][tx] = f2tff(W[(size_t)(by + ty + dy) * D_ + bx + tx]);
    __syncthreads();
    #pragma unroll
    for (int dy = 0; dy < 32; dy += 8) {
        int k = by + ((tx & ~7) | KPERM[tx & 7]);
        Wt[(size_t)(bx + ty + dy) * D_ + k] = t[tx][ty + dy];
    }
}

// ============================================================================
// TF32 HMMA GEMM, 4096x1024x1024. Inputs tf32-rounded + k-permuted.
// A smem [m][k'] stride 40, B smem [n][k'] stride 40 (both k-permuted so frag
// pairs (tg, tg+4) sit at positions (2tg, 2tg+1) -> float2 loads).
// 2-stage cp.async pipeline, 2 CTAs/SM. grid.z selects weight set (fused QKV).
// mode 0: plain store. mode 1: scatter to [B,H,S,Hd], store tf32-rounded.
// ============================================================================
struct GArgs {
    const float* A;
    const float* Bt[3];
    const float* bias[3];
    float* C[3];
    float scale[3];
    int mode;
};

static constexpr int GSS = 40;                          // smem row stride
static constexpr int G_TILE = 128 * GSS;                // floats per operand/stage
static constexpr int GEMM_SMEM = 2 * 2 * G_TILE * 4;    // 81920 B

__global__ __launch_bounds__(256, 2)
void gemm_hmma(GArgs args) {
    constexpr int NT = 1024 / 32;
    extern __shared__ float sh[];
    float* As = sh;                     // [2][128*40]
    float* Bs = sh + 2 * G_TILE;        // [2][128*40]
    const uint32_t sA = (uint32_t)__cvta_generic_to_shared(As);
    const uint32_t sB = (uint32_t)__cvta_generic_to_shared(Bs);

    const int tid  = threadIdx.x;
    const int warp = tid >> 5, lane = tid & 31;
    const int g = lane >> 2, tg = lane & 3;
    const int wm = warp >> 2, wn = warp & 3;
    const int bm = blockIdx.y * 128, bn = blockIdx.x * 128;
    const int z = blockIdx.z;
    const float* A    = args.A;
    const float* Bt   = args.Bt[z];
    const float* bias = args.bias[z];
    float* C          = args.C[z];
    const float scale = args.scale[z];

    auto issue = [&](int kt, int st) {
        #pragma unroll
        for (int j = 0; j < 4; ++j) {                   // 1024 chunks each
            int cc = tid + j * 256;
            int r = cc >> 3, o = cc & 7;
            uint32_t doff = (uint32_t)(st * G_TILE + r * GSS + o * 4) * 4;
            cp16(sA + doff, A  + (size_t)(bm + r) * 1024 + kt * 32 + o * 4);
            cp16(sB + doff, Bt + (size_t)(bn + r) * 1024 + kt * 32 + o * 4);
        }
        cp_commit();
    };

    float acc[4][4][4] = {};
    issue(0, 0);

    for (int kt = 0; kt < NT; ++kt) {
        if (kt + 1 < NT) { issue(kt + 1, (kt + 1) & 1); cp_wait<1>(); }
        else             { cp_wait<0>(); }
        __syncthreads();
        const float* as = As + (kt & 1) * G_TILE;
        const float* bs = Bs + (kt & 1) * G_TILE;

        #pragma unroll
        for (int kk = 0; kk < 32; kk += 8) {
            uint32_t af[4][4], bf[4][2];
            #pragma unroll
            for (int mt = 0; mt < 4; ++mt) {
                const float* a = as + (wm * 64 + mt * 16) * GSS + kk + 2 * tg;
                float2 L0 = *(const float2*)(a + g * GSS);
                float2 L1 = *(const float2*)(a + (g + 8) * GSS);
                af[mt][0] = __float_as_uint(L0.x);
                af[mt][1] = __float_as_uint(L1.x);
                af[mt][2] = __float_as_uint(L0.y);
                af[mt][3] = __float_as_uint(L1.y);
            }
            #pragma unroll
            for (int nt = 0; nt < 4; ++nt) {
                const float* b = bs + (wn * 32 + nt * 8 + g) * GSS + kk + 2 * tg;
                float2 Bv = *(const float2*)b;
                bf[nt][0] = __float_as_uint(Bv.x);
                bf[nt][1] = __float_as_uint(Bv.y);
            }
            #pragma unroll
            for (int mt = 0; mt < 4; ++mt)
                #pragma unroll
                for (int nt = 0; nt < 4; ++nt)
                    mma8(acc[mt][nt], af[mt], bf[nt]);
        }
        __syncthreads();
    }

    #pragma unroll
    for (int mt = 0; mt < 4; ++mt) {
        #pragma unroll
        for (int nt = 0; nt < 4; ++nt) {
            int r0 = bm + wm * 64 + mt * 16 + g;
            int c0 = bn + wn * 32 + nt * 8 + tg * 2;
            #pragma unroll
            for (int e = 0; e < 4; ++e) {
                int r = r0 + (e >> 1) * 8;
                int c = c0 + (e & 1);
                float v = (acc[mt][nt][e] + bias[c]) * scale;
                if (args.mode == 0) {
                    C[(size_t)r * 1024 + c] = v;
                } else {
                    int b = r >> 11, s = r & (S_ - 1);
                    int h = c >> 6, d = c & (HD_ - 1);
                    C[(((size_t)(b * H_ + h) * S_) + s) * HD_ + d] = f2tff(v);
                }
            }
        }
    }
}

// ============================================================================
// Flash attention: register softmax + in-register P layout transform (shuffle).
// CTA = 128 q-rows, 8 warps x (16 rows x 128 cols). K/V cp.async double-buffer.
// Epilogue stores Ab with k-permuted columns (consumed as GEMM2's k-dim).
// Smem: K [2][128][68], V [2][128][72].
// ============================================================================
static constexpr int KSS = 68, VSS = 72;
static constexpr int ATT_SMEM = (2 * 128 * KSS + 2 * 128 * VSS) * 4;  // 143360 B

__global__ __launch_bounds__(256, 1)
void attn_kernel(const float* __restrict__ Q, const float* __restrict__ K,
                 const float* __restrict__ V, float* __restrict__ O) {
    extern __shared__ float sh[];
    float* Ksf = sh;                       // [2][128*KSS]
    float* Vsf = sh + 2 * 128 * KSS;       // [2][128*VSS]
    const uint32_t sK = (uint32_t)__cvta_generic_to_shared(Ksf);
    const uint32_t sV = (uint32_t)__cvta_generic_to_shared(Vsf);

    const int tid  = threadIdx.x;
    const int warp = tid >> 5, lane = tid & 31;
    const int g = lane >> 2, tg = lane & 3;
    const int bh = blockIdx.y, qt = blockIdx.x;

    const float* Qp = Q + ((size_t)bh * S_ + qt * 128) * HD_;
    const float* Kp = K + (size_t)bh * S_ * HD_;
    const float* Vp = V + (size_t)bh * S_ * HD_;

    auto issue = [&](int kt, int st) {
        const float* Kt = Kp + (size_t)kt * 128 * HD_;
        const float* Vt = Vp + (size_t)kt * 128 * HD_;
        #pragma unroll
        for (int j = 0; j < 8; ++j) {       // 2048 chunks = full 128x64 tile
            int cc = tid + j * 256;
            int r = cc >> 4, o = cc & 15;
            cp16(sK + (uint32_t)(st * 128 * KSS + r * KSS + o * 4) * 4, Kt + r * 64 + o * 4);
            cp16(sV + (uint32_t)(st * 128 * VSS + r * VSS + o * 4) * 4, Vt + r * 64 + o * 4);
        }
        cp_commit();
    };

    issue(0, 0);

    // Stage Q through K stage-1 buffer (not yet loaded), build Q A-frags.
    float* Qst = Ksf + 128 * KSS;
    #pragma unroll
    for (int i = tid; i < 2048; i += 256) {
        int r = i >> 4, c4 = i & 15;
        float4 v = *(const float4*)(Qp + r * 64 + c4 * 4);
        *(float4*)(Qst + r * KSS + c4 * 4) = v;
    }
    __syncthreads();
    float qf[8][4];
    #pragma unroll
    for (int kk = 0; kk < 8; ++kk) {
        const float* q = Qst + (warp * 16) * KSS + kk * 8;
        qf[kk][0] = q[g * KSS + tg];
        qf[kk][1] = q[(g + 8) * KSS + tg];
        qf[kk][2] = q[g * KSS + tg + 4];
        qf[kk][3] = q[(g + 8) * KSS + tg + 4];
    }
    __syncthreads();

    float m0 = -1e30f, m1 = -1e30f, l0 = 0.f, l1 = 0.f;
    float oacc[8][4] = {};
    const int sl = (lane & ~3) + (tg >> 1);   // shuffle source lane for cols (tg, tg+4)
    const bool odd = tg & 1;

    constexpr int NT = S_ / 128;
    for (int kt = 0; kt < NT; ++kt) {
        if (kt + 1 < NT) { issue(kt + 1, (kt + 1) & 1); cp_wait<1>(); }
        else             { cp_wait<0>(); }
        __syncthreads();
        const float* Ksb = Ksf + (kt & 1) * 128 * KSS;
        const float* Vsb = Vsf + (kt & 1) * 128 * VSS;

        // S = Q @ K^T : 16 rows x 128 cols per warp
        float sacc[16][4] = {};
        #pragma unroll
        for (int nt = 0; nt < 16; ++nt) {
            const float* kb = Ksb + (nt * 8 + g) * KSS;
            #pragma unroll
            for (int kk = 0; kk < 8; ++kk)
                mma8f(sacc[nt], qf[kk], kb[kk * 8 + tg], kb[kk * 8 + tg + 4]);
        }

        // Register softmax (rows g / g+8 per lane)
        float mx0 = -1e30f, mx1 = -1e30f;
        #pragma unroll
        for (int nt = 0; nt < 16; ++nt) {
            mx0 = fmaxf(mx0, fmaxf(sacc[nt][0], sacc[nt][1]));
            mx1 = fmaxf(mx1, fmaxf(sacc[nt][2], sacc[nt][3]));
        }
        mx0 = fmaxf(mx0, __shfl_xor_sync(0xffffffffu, mx0, 1));
        mx0 = fmaxf(mx0, __shfl_xor_sync(0xffffffffu, mx0, 2));
        mx1 = fmaxf(mx1, __shfl_xor_sync(0xffffffffu, mx1, 1));
        mx1 = fmaxf(mx1, __shfl_xor_sync(0xffffffffu, mx1, 2));
        float nm0 = fmaxf(m0, mx0), nm1 = fmaxf(m1, mx1);
        float al0 = __expf(m0 - nm0), al1 = __expf(m1 - nm1);
        m0 = nm0; m1 = nm1;

        float s0 = 0.f, s1 = 0.f;
        #pragma unroll
        for (int nt = 0; nt < 16; ++nt) {
            float p0 = __expf(sacc[nt][0] - m0);
            float p1 = __expf(sacc[nt][1] - m0);
            float p2 = __expf(sacc[nt][2] - m1);
            float p3 = __expf(sacc[nt][3] - m1);
            s0 += p0 + p1; s1 += p2 + p3;
            // C-frag (cols 2tg,2tg+1) -> A-frag (cols tg, tg+4) lane exchange
            float v0 = __shfl_sync(0xffffffffu, p0, sl);
            float v1 = __shfl_sync(0xffffffffu, p1, sl);
            float v2 = __shfl_sync(0xffffffffu, p2, sl);
            float v3 = __shfl_sync(0xffffffffu, p3, sl);
            float w0 = __shfl_sync(0xffffffffu, p0, sl + 2);
            float w1 = __shfl_sync(0xffffffffu, p1, sl + 2);
            float w2 = __shfl_sync(0xffffffffu, p2, sl + 2);
            float w3 = __shfl_sync(0xffffffffu, p3, sl + 2);
            sacc[nt][0] = f2tff(odd ? v1 : v0);   // P[g   ][8nt+tg  ]
            sacc[nt][1] = f2tff(odd ? v3 : v2);   // P[g+8 ][8nt+tg  ]
            sacc[nt][2] = f2tff(odd ? w1 : w0);   // P[g   ][8nt+tg+4]
            sacc[nt][3] = f2tff(odd ? w3 : w2);   // P[g+8 ][8nt+tg+4]
        }
        s0 += __shfl_xor_sync(0xffffffffu, s0, 1);
        s0 += __shfl_xor_sync(0xffffffffu, s0, 2);
        s1 += __shfl_xor_sync(0xffffffffu, s1, 1);
        s1 += __shfl_xor_sync(0xffffffffu, s1, 2);
        l0 = l0 * al0 + s0;
        l1 = l1 * al1 + s1;

        // O rescale + O += P @ V
        #pragma unroll
        for (int nt = 0; nt < 8; ++nt) {
            oacc[nt][0] *= al0; oacc[nt][1] *= al0;
            oacc[nt][2] *= al1; oacc[nt][3] *= al1;
        }
        #pragma unroll
        for (int nt = 0; nt < 8; ++nt) {
            #pragma unroll
            for (int kk = 0; kk < 16; ++kk) {
                const float* vb = Vsb + kk * 8 * VSS + nt * 8 + g;
                mma8f(oacc[nt], sacc[kk], vb[tg * VSS], vb[(tg + 4) * VSS]);
            }
        }
        __syncthreads();
    }

    const float inv0 = 1.f / l0, inv1 = 1.f / l1;
    const int b = bh >> 4, h = bh & (H_ - 1);
    const int r0 = qt * 128 + warp * 16 + g;
    float* Op = O + ((size_t)b * S_ + r0) * D_ + h * HD_;
    // Store with k-permuted columns (Ab is GEMM2's k-dim)
    const int pc0 = KPERM[2 * tg], pc1 = KPERM[2 * tg + 1];
    #pragma unroll
    for (int nt = 0; nt < 8; ++nt) {
        Op[nt * 8 + pc0]                   = f2tff(oacc[nt][0] * inv0);
        Op[nt * 8 + pc1]                   = f2tff(oacc[nt][1] * inv0);
        Op[(size_t)8 * D_ + nt * 8 + pc0]  = f2tff(oacc[nt][2] * inv1);
        Op[(size_t)8 * D_ + nt * 8 + pc1]  = f2tff(oacc[nt][3] * inv1);
    }
}

// ============================================================================
extern "C" void kernel_launch(void* const* d_in, const int* in_sizes, int n_in,
                              void* d_out, int out_size) {
    (void)in_sizes; (void)n_in; (void)out_size;
    const float* x  = (const float*)d_in[0];
    const float* Wq = (const float*)d_in[1];
    const float* bq = (const float*)d_in[2];
    const float* Wk = (const float*)d_in[3];
    const float* bk = (const float*)d_in[4];
    const float* Wv = (const float*)d_in[5];
    const float* bv = (const float*)d_in[6];
    const float* Wo = (const float*)d_in[7];
    const float* bo = (const float*)d_in[8];
    float* out = (float*)d_out;

    float *Qb, *Kb, *Vb, *Ab, *Xr, *Wqt, *Wkt, *Wvt, *Wot;
    cudaGetSymbolAddress((void**)&Qb, g_Q);
    cudaGetSymbolAddress((void**)&Kb, g_K);
    cudaGetSymbolAddress((void**)&Vb, g_V);
    cudaGetSymbolAddress((void**)&Ab, g_att);
    cudaGetSymbolAddress((void**)&Xr, g_x);
    cudaGetSymbolAddress((void**)&Wqt, g_Wq);
    cudaGetSymbolAddress((void**)&Wkt, g_Wk);
    cudaGetSymbolAddress((void**)&Wvt, g_Wv);
    cudaGetSymbolAddress((void**)&Wot, g_Wo);

    const int nX = M_ROWS * D_;
    round_perm_kernel<<<nX / 1024, 256>>>(x, Xr, nX);
    const dim3 tgrid(32, 32);
    transpose_round_kernel<<<tgrid, 256>>>(Wq, Wqt);
    transpose_round_kernel<<<tgrid, 256>>>(Wk, Wkt);
    transpose_round_kernel<<<tgrid, 256>>>(Wv, Wvt);
    transpose_round_kernel<<<tgrid, 256>>>(Wo, Wot);

    cudaFuncSetAttribute(gemm_hmma, cudaFuncAttributeMaxDynamicSharedMemorySize, GEMM_SMEM);
    cudaFuncSetAttribute(attn_kernel, cudaFuncAttributeMaxDynamicSharedMemorySize, ATT_SMEM);

    // Fused QKV projections (z = 0,1,2)
    GArgs qkv;
    qkv.A = Xr;
    qkv.Bt[0] = Wqt; qkv.Bt[1] = Wkt; qkv.Bt[2] = Wvt;
    qkv.bias[0] = bq; qkv.bias[1] = bk; qkv.bias[2] = bv;
    qkv.C[0] = Qb; qkv.C[1] = Kb; qkv.C[2] = Vb;
    qkv.scale[0] = 0.125f; qkv.scale[1] = 1.0f; qkv.scale[2] = 1.0f;
    qkv.mode = 1;
    gemm_hmma<<<dim3(8, 32, 3), 256, GEMM_SMEM>>>(qkv);

    attn_kernel<<<dim3(S_ / 128, B_ * H_), 256, ATT_SMEM>>>(Qb, Kb, Vb, Ab);

    // Output projection
    GArgs og;
    og.A = Ab;
    og.Bt[0] = Wot; og.Bt[1] = Wot; og.Bt[2] = Wot;
    og.bias[0] = bo; og.bias[1] = bo; og.bias[2] = bo;
    og.C[0] = out; og.C[1] = out; og.C[2] = out;
    og.scale[0] = 1.0f; og.scale[1] = 1.0f; og.scale[2] = 1.0f;
    og.mode = 0;
    gemm_hmma<<<dim3(8, 32, 1), 256, GEMM_SMEM>>>(og);
}